// round 15
// baseline (speedup 1.0000x reference)
#include <cuda_runtime.h>
#include <cuda_bf16.h>
#include <cstdint>
#include <math.h>

// Problem constants (B=4, T=512, H=1024, V=32000)
#define R_TOK 2048
#define HID   1024
#define VOC   32000
#define NSEQ  4
#define TSEQ  512

#define KCAT  3072              // [hi | hi | lo] x [hi | lo | hi] concatenated K
#define BM    128
#define BN    256
#define NBLK  (VOC / BN)        // 125
#define MPAIR 8                 // 16 m-blocks in pairs
#define NCHUNK 48               // chunks per tile
#define NSTAGE 4
#define STAGE_BYTES 49152       // A 16KB + B 32KB
#define SMEM_TOTAL (2048 + NSTAGE * STAGE_BYTES)   // 198656

#define BETA 0.1f

// idesc: F32 accum, bf16 A/B, K-major both, M=128, N=128
#define MMA_IDESC 0x08200490u

// tcgen05 only exists in arch-specific (sm_103a/f) compilation passes.
#if defined(__CUDA_ARCH_FEAT_SM103_ALL) || defined(__CUDA_ARCH_FEAT_SM100_ALL) || \
    defined(__CUDA_ARCH_FEAT_SM101_ALL) || \
    (defined(__CUDA_ARCH_SPECIFIC__) && (__CUDA_ARCH_SPECIFIC__ >= 1000))
#define HAS_TC 1
#else
#define HAS_TC 0
#endif

// ------------------------------- scratch -----------------------------------
__device__ float g_pm[2][R_TOK][NBLK];
__device__ float g_ps[2][R_TOK][NBLK];
__device__ float g_tgt[2][R_TOK];
__device__ float g_tok[2][R_TOK];
__device__ int   g_target[R_TOK];
__device__ int   g_mask[R_TOK];
__device__ int   g_labels[NSEQ];

__device__ __align__(16) __nv_bfloat16 g_A[2][R_TOK][KCAT];   // 25 MB
__device__ __align__(16) __nv_bfloat16 g_B[2][VOC][KCAT];     // 393 MB

// ------------------------------- PTX helpers -------------------------------
__device__ __forceinline__ uint32_t smem_u32(const void* p) {
    uint32_t a;
    asm("{ .reg .u64 t; cvta.to.shared.u64 t, %1; cvt.u32.u64 %0, t; }"
        : "=r"(a) : "l"(p));
    return a;
}

__device__ __forceinline__ uint32_t sw128(uint32_t o) {
    return o ^ ((o >> 3) & 0x70u);
}

__device__ __forceinline__ void cp16(uint32_t s, const void* g) {
    asm volatile("cp.async.cg.shared.global [%0], [%1], 16;" :: "r"(s), "l"(g));
}

#if HAS_TC
__device__ __forceinline__ uint32_t elect1() {
    uint32_t r;
    asm volatile("{\n\t.reg .pred p;\n\telect.sync _|p, 0xFFFFFFFF;\n\t"
                 "selp.b32 %0, 1, 0, p;\n\t}" : "=r"(r));
    return r;
}

// SW128 K-major descriptor: layout=2, version=1, SBO=64, LBO=1
__device__ __forceinline__ uint64_t mk_desc(uint32_t addr) {
    return ((uint64_t)2 << 61) | ((uint64_t)1 << 46) | ((uint64_t)64 << 32) |
           ((uint64_t)1 << 16) | ((uint64_t)(addr >> 4) & 0x3FFF);
}

__device__ __forceinline__ void mma_f16_ss(uint32_t d, uint64_t a, uint64_t b,
                                           uint32_t en) {
    asm volatile(
        "{\n\t.reg .pred p;\n\tsetp.ne.u32 p, %4, 0;\n\t"
        "tcgen05.mma.cta_group::1.kind::f16 [%0], %1, %2, %3, {%5, %5, %5, %5}, p;\n\t}"
        :: "r"(d), "l"(a), "l"(b), "r"(MMA_IDESC), "r"(en), "r"(0u)
        : "memory");
}

__device__ __forceinline__ void tc_commit(uint32_t m) {
    asm volatile(
        "tcgen05.commit.cta_group::1.mbarrier::arrive::one.shared::cluster.b64 [%0];"
        :: "r"(m) : "memory");
}

__device__ __forceinline__ void cpasync_arrive_noinc(uint32_t m) {
    asm volatile("cp.async.mbarrier.arrive.noinc.shared::cta.b64 [%0];"
                 :: "r"(m) : "memory");
}

#define LDTM_X32(r, addr) \
    asm volatile( \
        "tcgen05.ld.sync.aligned.32x32b.x32.b32 " \
        "{%0, %1, %2, %3, %4, %5, %6, %7, " \
        " %8, %9, %10, %11, %12, %13, %14, %15, " \
        " %16, %17, %18, %19, %20, %21, %22, %23, " \
        " %24, %25, %26, %27, %28, %29, %30, %31}, [%32];" \
        : "=r"((r)[0]),  "=r"((r)[1]),  "=r"((r)[2]),  "=r"((r)[3]), \
          "=r"((r)[4]),  "=r"((r)[5]),  "=r"((r)[6]),  "=r"((r)[7]), \
          "=r"((r)[8]),  "=r"((r)[9]),  "=r"((r)[10]), "=r"((r)[11]), \
          "=r"((r)[12]), "=r"((r)[13]), "=r"((r)[14]), "=r"((r)[15]), \
          "=r"((r)[16]), "=r"((r)[17]), "=r"((r)[18]), "=r"((r)[19]), \
          "=r"((r)[20]), "=r"((r)[21]), "=r"((r)[22]), "=r"((r)[23]), \
          "=r"((r)[24]), "=r"((r)[25]), "=r"((r)[26]), "=r"((r)[27]), \
          "=r"((r)[28]), "=r"((r)[29]), "=r"((r)[30]), "=r"((r)[31]) \
        : "r"(addr))
#endif  // HAS_TC

__device__ __forceinline__ void mbar_init(uint32_t m, uint32_t cnt) {
    asm volatile("mbarrier.init.shared.b64 [%0], %1;" :: "r"(m), "r"(cnt) : "memory");
}

__device__ __forceinline__ void mbar_wait(uint32_t m, uint32_t parity) {
    asm volatile(
        "{\n\t.reg .pred P;\n\t"
        "W_%=:\n\t"
        "mbarrier.try_wait.parity.acquire.cta.shared::cta.b64 P, [%0], %1;\n\t"
        "@!P bra W_%=;\n\t}"
        :: "r"(m), "r"(parity) : "memory");
}

#if !HAS_TC
// mma.sync fallback helpers (baseline sm_80+ instructions)
__device__ __forceinline__ void ldsm4(uint32_t& r0, uint32_t& r1,
                                      uint32_t& r2, uint32_t& r3, uint32_t a) {
    asm volatile("ldmatrix.sync.aligned.m8n8.x4.shared.b16 {%0,%1,%2,%3}, [%4];"
                 : "=r"(r0), "=r"(r1), "=r"(r2), "=r"(r3) : "r"(a));
}

__device__ __forceinline__ void hmma(float* c, uint32_t a0, uint32_t a1,
                                     uint32_t a2, uint32_t a3,
                                     uint32_t b0, uint32_t b1) {
    asm volatile(
        "mma.sync.aligned.m16n8k16.row.col.f32.bf16.bf16.f32 "
        "{%0,%1,%2,%3}, {%4,%5,%6,%7}, {%8,%9}, {%0,%1,%2,%3};"
        : "+f"(c[0]), "+f"(c[1]), "+f"(c[2]), "+f"(c[3])
        : "r"(a0), "r"(a1), "r"(a2), "r"(a3), "r"(b0), "r"(b1));
}
#endif

// -----------------------------------------------------------------------------
// Phase 0: dtype detection + normalization of target / labels (proven in R2)
// -----------------------------------------------------------------------------
__global__ void detect_kernel(const void* __restrict__ tgt_raw,
                              const void* __restrict__ lab_raw)
{
    __shared__ int s_t64;
    const int tid = threadIdx.x;
    const int* t32 = (const int*)tgt_raw;

    if (tid == 0) {
        bool t64 = true;
        for (int k = 0; k < 64; k++)
            if (t32[2 * k + 1] != 0) { t64 = false; break; }
        s_t64 = t64 ? 1 : 0;

        const unsigned int*  li = (const unsigned int*)lab_raw;
        const unsigned char* lb = (const unsigned char*)lab_raw;
        int done = 0;
        {
            bool isf = true;
            for (int b = 0; b < 4; b++) {
                unsigned int u = li[b];
                if (u != 0u && u != 0x3f800000u) { isf = false; break; }
            }
            if (isf) {
                for (int b = 0; b < 4; b++) g_labels[b] = (li[b] != 0u) ? 1 : 0;
                done = 1;
            }
        }
        if (!done && li[0] <= 1u) {
            bool isi = true;
            for (int b = 1; b < 4; b++)
                if (li[b] > 1u) { isi = false; break; }
            if (isi) {
                for (int b = 0; b < 4; b++) g_labels[b] = (int)li[b];
                done = 1;
            }
        }
        if (!done)
            for (int b = 0; b < 4; b++) g_labels[b] = (lb[b] != 0) ? 1 : 0;
    }
    __syncthreads();

    const bool t64 = (s_t64 != 0);
    for (int i = tid; i < R_TOK; i += blockDim.x) {
        int v = t64 ? t32[2 * i] : t32[i];
        const int ign = (v == -100);
        if (v < 0) v = 0;
        if (v > VOC - 1) v = VOC - 1;
        g_target[i] = v;
        g_mask[i]   = ign ? 0 : 1;
    }
}

// -----------------------------------------------------------------------------
// Phase 0b: fp32 -> bf16 hi/lo split into concatenated-K operands.
// A' = [Xhi | Xhi | Xlo], B' = [Whi | Wlo | Whi]
// -----------------------------------------------------------------------------
__device__ __forceinline__ void split4(const float4 v,
                                       __nv_bfloat162& h01, __nv_bfloat162& h23,
                                       __nv_bfloat162& l01, __nv_bfloat162& l23)
{
    __nv_bfloat16 h0 = __float2bfloat16_rn(v.x);
    __nv_bfloat16 h1 = __float2bfloat16_rn(v.y);
    __nv_bfloat16 h2 = __float2bfloat16_rn(v.z);
    __nv_bfloat16 h3 = __float2bfloat16_rn(v.w);
    __nv_bfloat16 l0 = __float2bfloat16_rn(v.x - __bfloat162float(h0));
    __nv_bfloat16 l1 = __float2bfloat16_rn(v.y - __bfloat162float(h1));
    __nv_bfloat16 l2 = __float2bfloat16_rn(v.z - __bfloat162float(h2));
    __nv_bfloat16 l3 = __float2bfloat16_rn(v.w - __bfloat162float(h3));
    h01 = __nv_bfloat162(h0, h1); h23 = __nv_bfloat162(h2, h3);
    l01 = __nv_bfloat162(l0, l1); l23 = __nv_bfloat162(l2, l3);
}

__global__ void convert_w_kernel(const float* __restrict__ w0,
                                 const float* __restrict__ w1)
{
    const int QPR = HID / 4;                     // 256 quads/row
    const int per_model = VOC * QPR;
    int id = blockIdx.x * blockDim.x + threadIdx.x;
    if (id >= 2 * per_model) return;
    const int m = id / per_model;
    const int r = (id % per_model) / QPR;
    const int q = id % QPR;
    const float* W = m ? w1 : w0;
    const float4 v = *(const float4*)(W + (size_t)r * HID + q * 4);
    __nv_bfloat162 h01, h23, l01, l23;
    split4(v, h01, h23, l01, l23);
    __nv_bfloat16* row = &g_B[m][r][0];
    *(__nv_bfloat162*)(row + q * 4 + 0)        = h01;   // seg0: hi
    *(__nv_bfloat162*)(row + q * 4 + 2)        = h23;
    *(__nv_bfloat162*)(row + HID + q * 4 + 0)  = l01;   // seg1: lo
    *(__nv_bfloat162*)(row + HID + q * 4 + 2)  = l23;
    *(__nv_bfloat162*)(row + 2*HID + q * 4 + 0) = h01;  // seg2: hi
    *(__nv_bfloat162*)(row + 2*HID + q * 4 + 2) = h23;
}

__global__ void convert_x_kernel(const float* __restrict__ x0,
                                 const float* __restrict__ x1)
{
    const int QPR = HID / 4;
    const int per_model = R_TOK * QPR;
    int id = blockIdx.x * blockDim.x + threadIdx.x;
    if (id >= 2 * per_model) return;
    const int m = id / per_model;
    const int r = (id % per_model) / QPR;
    const int q = id % QPR;
    const float* X = m ? x1 : x0;
    const float4 v = *(const float4*)(X + (size_t)r * HID + q * 4);
    __nv_bfloat162 h01, h23, l01, l23;
    split4(v, h01, h23, l01, l23);
    __nv_bfloat16* row = &g_A[m][r][0];
    *(__nv_bfloat162*)(row + q * 4 + 0)        = h01;   // seg0: hi
    *(__nv_bfloat162*)(row + q * 4 + 2)        = h23;
    *(__nv_bfloat162*)(row + HID + q * 4 + 0)  = h01;   // seg1: hi
    *(__nv_bfloat162*)(row + HID + q * 4 + 2)  = h23;
    *(__nv_bfloat162*)(row + 2*HID + q * 4 + 0) = l01;  // seg2: lo
    *(__nv_bfloat162*)(row + 2*HID + q * 4 + 2) = l23;
}

// -----------------------------------------------------------------------------
// Phase A: bf16 GEMM. Each CTA does TWO 128x256 M-tiles of one N-block
// (96 chunks, D0/D1 in TMEM cols 0-255/256-511). Warp-specialized: warps 1-2
// load, warp 0 issues MMAs, warps 4-7 run tile0's epilogue OVERLAPPED with
// tile1's mainloop; warps 0-3 run tile1's epilogue at the end.
// grid.x = 2*MPAIR*NBLK = 2000; block = 256.
// -----------------------------------------------------------------------------
extern __shared__ char dsmem[];

__global__ void __launch_bounds__(256, 1)
gemm_tc_kernel(const float* __restrict__ b_pol, const float* __restrict__ b_ref)
{
    const int bx    = blockIdx.x;
    const int mpair = bx & (MPAIR - 1);
    const int t     = bx >> 3;
    const int nblk  = t % NBLK;
    const int model = t / NBLK;
    const int rb0   = mpair * 256;
    const int rb1   = rb0 + 128;
    const int cb    = nblk * BN;
    const float* __restrict__ Bv = model ? b_ref : b_pol;

    const int tid = threadIdx.x;
    const int wid = tid >> 5;
    const int lid = tid & 31;

    const uint32_t smem_base = smem_u32(dsmem);
    float* bias_s = (float*)(dsmem + 1024);

    const char* Agm0 = (const char*)&g_A[model][rb0][0];
    const char* Agm1 = (const char*)&g_A[model][rb1][0];
    const char* Bgm  = (const char*)&g_B[model][cb][0];
    const size_t rowbytes = (size_t)KCAT * 2;

#if HAS_TC
    // ======================= tcgen05 path (sm_103a) ==========================
    // mbarriers: mma[s] at +s*8 (cnt 1); tile_done0 at +48; tile_done1 at +56;
    // full[s] at +64+s*8 (cnt 64). tmem ptr at +32. bias at +1024.
    // Stages at +2048.
    if (tid == 0) {
        #pragma unroll
        for (int s = 0; s < NSTAGE; s++) {
            mbar_init(smem_base + s * 8, 1);
            mbar_init(smem_base + 64 + s * 8, 64);
        }
        mbar_init(smem_base + 48, 1);
        mbar_init(smem_base + 56, 1);
    }
    if (wid == 0) {
        asm volatile(
            "tcgen05.alloc.cta_group::1.sync.aligned.shared::cta.b32 [%0], %1;"
            :: "r"(smem_base + 32), "r"(512) : "memory");
    }
    if (tid < BN) bias_s[tid] = Bv[cb + tid];
    __syncthreads();
    uint32_t tmem;
    asm volatile("ld.shared.b32 %0, [%1];" : "=r"(tmem) : "r"(smem_base + 32));

    // per-tile epilogue (bias + online LSE + target gather), one warp = 32 rows
    auto tc_epilogue = [&](int row, uint32_t dtm) {
        const int tg  = g_target[row];
        const int loc = tg - cb;
        float rmax = -INFINITY, rsum = 0.f, tl = 0.f;
        uint32_t r[32];
        #pragma unroll
        for (int b = 0; b < 8; b++) {
            LDTM_X32(r, dtm + b * 32);
            asm volatile("tcgen05.wait::ld.sync.aligned;" ::: "memory");
            float v[32];
            float bmax = -INFINITY;
            #pragma unroll
            for (int j = 0; j < 32; j++) {
                v[j] = __uint_as_float(r[j]) + bias_s[b * 32 + j];
                bmax = fmaxf(bmax, v[j]);
            }
            const float nm = fmaxf(rmax, bmax);
            rsum *= __expf(rmax - nm);
            float s = 0.f;
            #pragma unroll
            for (int j = 0; j < 32; j++) s += __expf(v[j] - nm);
            rsum += s;
            rmax = nm;
            if ((loc >> 5) == b) {
                #pragma unroll
                for (int j = 0; j < 32; j++)
                    if ((loc & 31) == j) tl = v[j];
            }
        }
        g_pm[model][row][nblk] = rmax;
        g_ps[model][row][nblk] = rsum;
        if (loc >= 0 && loc < BN) g_tgt[model][row] = tl;
    };

    if (wid == 1 || wid == 2) {
        // ---------------- loader warps: 48 cp16/thread/chunk ----------------
        const int ltid = tid - 32;                  // 0..63
        const int xq   = ltid & 7;
        const int r0   = ltid >> 3;
        const uint32_t sw_x  = (uint32_t)(xq * 16) ^ (uint32_t)((r0 & 7) * 16);
        const uint32_t aoff0 = (uint32_t)r0 * 128 + sw_x;
        const size_t   tbase = (size_t)r0 * rowbytes + xq * 16;
        const char*    agm_t[2] = { Agm0 + tbase, Agm1 + tbase };
        const char*    bgm0  = Bgm + tbase;
        const size_t   gstep = 8 * rowbytes;

        for (int c = 0; c < 2 * NCHUNK; c++) {
            const int s  = c & 3;
            const int cl = (c < NCHUNK) ? c : c - NCHUNK;
            if (c >= NSTAGE)
                mbar_wait(smem_base + s * 8, (uint32_t)(((c >> 2) - 1) & 1));
            const uint32_t abase = smem_base + 2048 + s * STAGE_BYTES + aoff0;
            const uint32_t bbase = abase + 16384;
            const char* ag = agm_t[c >= NCHUNK] + (size_t)cl * 128;
            const char* bg = bgm0 + (size_t)cl * 128;
            #pragma unroll
            for (int i = 0; i < 16; i++)            // A rows r0+8i (128 rows)
                cp16(abase + i * 1024, ag + i * gstep);
            #pragma unroll
            for (int i = 0; i < 32; i++)            // B rows r0+8i (256 rows)
                cp16(bbase + i * 1024, bg + i * gstep);
            cpasync_arrive_noinc(smem_base + 64 + s * 8);
        }
    } else if (wid == 0) {
        // ---------------- issuer warp ----------------
        const uint32_t is_issuer = elect1();
        for (int c = 0; c < 2 * NCHUNK; c++) {
            const int s  = c & 3;
            const int cl = (c < NCHUNK) ? c : c - NCHUNK;
            mbar_wait(smem_base + 64 + s * 8, (uint32_t)((c >> 2) & 1));
            if (is_issuer) {
                asm volatile("fence.proxy.async.shared::cta;" ::: "memory");
                const uint32_t dt   = (c < NCHUNK) ? 0u : 256u;
                const uint32_t base = smem_base + 2048 + s * STAGE_BYTES;
                const uint64_t ad = mk_desc(base);
                const uint64_t b0 = mk_desc(base + 16384);
                const uint64_t b1 = mk_desc(base + 32768);
                #pragma unroll
                for (int ks = 0; ks < 4; ks++) {
                    const uint32_t en = (cl > 0 || ks > 0) ? 1u : 0u;
                    mma_f16_ss(tmem + dt,       ad + ks * 2, b0 + ks * 2, en);
                    mma_f16_ss(tmem + dt + 128, ad + ks * 2, b1 + ks * 2, en);
                }
                tc_commit(smem_base + s * 8);
                if (c == NCHUNK - 1)     tc_commit(smem_base + 48);  // tile0 done
                if (c == 2 * NCHUNK - 1) tc_commit(smem_base + 56);  // tile1 done
            }
        }
    } else if (wid >= 4) {
        // -------- tile0 epilogue, OVERLAPPED with tile1 mainloop --------
        mbar_wait(smem_base + 48, 0u);
        asm volatile("tcgen05.fence::after_thread_sync;" ::: "memory");
        tc_epilogue(rb0 + (wid - 4) * 32 + lid, tmem);
    }

    // tail: tile1 epilogue on warps 0-3
    mbar_wait(smem_base + 56, 0u);
    asm volatile("tcgen05.fence::after_thread_sync;" ::: "memory");
    if (wid < 4)
        tc_epilogue(rb1 + wid * 32 + lid, tmem + 256);

    __syncthreads();
    if (wid == 0) {
        asm volatile("tcgen05.dealloc.cta_group::1.sync.aligned.b32 %0, %1;"
                     :: "r"(tmem), "r"(512));
    }
#else
    // ================== mma.sync fallback (baseline sm_103) ==================
    auto load_chunk = [&](const char* Ag, int c, int s) {
        const uint32_t abase = smem_base + 2048 + s * STAGE_BYTES;
        const uint32_t bbase = abase + 16384;
        const char* ag = Ag + (size_t)c * 128;
        const char* bg = Bgm + (size_t)c * 128;
        #pragma unroll
        for (int i = 0; i < 4; i++) {               // A: 1024 x 16B
            const int q = tid + 256 * i;
            const int row = q >> 3, x = q & 7;
            cp16(abase + sw128(row * 128 + x * 16), ag + (size_t)row * rowbytes + x * 16);
        }
        #pragma unroll
        for (int i = 0; i < 8; i++) {               // B: 2048 x 16B
            const int q = tid + 256 * i;
            const int row = q >> 3, x = q & 7;
            cp16(bbase + sw128(row * 128 + x * 16), bg + (size_t)row * rowbytes + x * 16);
        }
        asm volatile("cp.async.commit_group;" ::: "memory");
    };

    const int wr = wid & 3;
    const int wc = wid >> 2;
    const int koffA = (lid >> 4) * 16;
    const int xA    = (lid & 7) << 4;
    const int rA0   = wr * 32 + (lid & 15);
    const int rbB   = (lid >> 4) * 8 + (lid & 7);
    const int koffB = ((lid >> 3) & 1) * 16;
    const int xB    = (rbB & 7) << 4;
    const int brow  = wc * 128 + rbB;

    for (int tile = 0; tile < 2; tile++) {
        const int rb = rb0 + tile * 128;
        const char* Ag = tile ? Agm1 : Agm0;

        load_chunk(Ag, 0, 0);
        load_chunk(Ag, 1, 1);
        load_chunk(Ag, 2, 2);

        float acc[2][16][4];
        #pragma unroll
        for (int a = 0; a < 2; a++)
            #pragma unroll
            for (int b = 0; b < 16; b++)
                #pragma unroll
                for (int d = 0; d < 4; d++) acc[a][b][d] = 0.f;

        for (int c = 0; c < NCHUNK; c++) {
            asm volatile("cp.async.wait_group 2;" ::: "memory");
            __syncthreads();
            const uint32_t sb  = smem_base + 2048 + (c & 3) * STAGE_BYTES;
            const uint32_t aA0 = sb + rA0 * 128;
            const uint32_t aA1 = sb + (rA0 + 16) * 128;
            const uint32_t bB  = sb + 16384 + brow * 128;
            #pragma unroll
            for (int ks = 0; ks < 4; ks++) {
                const int kb = ks * 32;
                uint32_t a0[4], a1[4];
                ldsm4(a0[0], a0[1], a0[2], a0[3], aA0 + ((kb + koffA) ^ xA));
                ldsm4(a1[0], a1[1], a1[2], a1[3], aA1 + ((kb + koffA) ^ xA));
                #pragma unroll
                for (int p = 0; p < 8; p++) {
                    uint32_t b0, b1, b2, b3;
                    ldsm4(b0, b1, b2, b3, bB + p * 2048 + ((kb + koffB) ^ xB));
                    hmma(acc[0][2*p],     a0[0], a0[1], a0[2], a0[3], b0, b1);
                    hmma(acc[1][2*p],     a1[0], a1[1], a1[2], a1[3], b0, b1);
                    hmma(acc[0][2*p + 1], a0[0], a0[1], a0[2], a0[3], b2, b3);
                    hmma(acc[1][2*p + 1], a1[0], a1[1], a1[2], a1[3], b2, b3);
                }
            }
            const int n = c + 3;
            if (n < NCHUNK) load_chunk(Ag, n, n & 3);
            else asm volatile("cp.async.commit_group;" ::: "memory");
        }
        asm volatile("cp.async.wait_group 0;" ::: "memory");
        __syncthreads();

        float* bias_f = (float*)(dsmem + 1024);
        if (tid < BN) bias_f[tid] = Bv[cb + tid];
        float* rmx = (float*)(dsmem + 2048);
        float* rsm = rmx + 256;
        float* rtl = rsm + 256;
        __syncthreads();

        #pragma unroll
        for (int mi = 0; mi < 2; mi++) {
            #pragma unroll
            for (int half = 0; half < 2; half++) {
                const int rloc = wr * 32 + mi * 16 + (lid >> 2) + half * 8;
                const int loc  = g_target[rb + rloc] - cb;
                float m = -INFINITY;
                #pragma unroll
                for (int nt = 0; nt < 16; nt++) {
                    #pragma unroll
                    for (int j = 0; j < 2; j++) {
                        const int gcol = wc * 128 + nt * 8 + (lid & 3) * 2 + j;
                        m = fmaxf(m, acc[mi][nt][half * 2 + j] + bias_f[gcol]);
                    }
                }
                float s = 0.f, tl = 0.f;
                #pragma unroll
                for (int nt = 0; nt < 16; nt++) {
                    #pragma unroll
                    for (int j = 0; j < 2; j++) {
                        const int gcol = wc * 128 + nt * 8 + (lid & 3) * 2 + j;
                        const float v = acc[mi][nt][half * 2 + j] + bias_f[gcol];
                        s += __expf(v - m);
                        if (gcol == loc) tl = v;
                    }
                }
                #pragma unroll
                for (int off = 1; off <= 2; off <<= 1) {
                    const float mo = __shfl_xor_sync(0xffffffffu, m, off);
                    const float so = __shfl_xor_sync(0xffffffffu, s, off);
                    const float nm = fmaxf(m, mo);
                    s = s * __expf(m - nm) + so * __expf(mo - nm);
                    m = nm;
                    tl += __shfl_xor_sync(0xffffffffu, tl, off);
                }
                if ((lid & 3) == 0) {
                    rmx[rloc * 2 + wc] = m;
                    rsm[rloc * 2 + wc] = s;
                    rtl[rloc * 2 + wc] = tl;
                }
            }
        }
        __syncthreads();

        if (tid < 128) {
            const int row = rb + tid;
            const float m0 = rmx[tid * 2], m1 = rmx[tid * 2 + 1];
            const float M  = fmaxf(m0, m1);
            const float S  = rsm[tid * 2] * __expf(m0 - M) +
                             rsm[tid * 2 + 1] * __expf(m1 - M);
            g_pm[model][row][nblk] = M;
            g_ps[model][row][nblk] = S;
            const int loc = g_target[row] - cb;
            if (loc >= 0 && loc < BN)
                g_tgt[model][row] = rtl[tid * 2] + rtl[tid * 2 + 1];
        }
        __syncthreads();
    }
#endif
}

// -----------------------------------------------------------------------------
// Phase B: merge the 125 per-nblock partials -> full LSE -> per-token logprob.
// -----------------------------------------------------------------------------
__global__ void lse_reduce_kernel()
{
    const int row = blockIdx.x;
    const int m   = blockIdx.y;
    const int tid = threadIdx.x;

    __shared__ float sm[4];

    float pm = -INFINITY;
    if (tid < NBLK) pm = g_pm[m][row][tid];

    float mv = pm;
    #pragma unroll
    for (int off = 16; off >= 1; off >>= 1)
        mv = fmaxf(mv, __shfl_xor_sync(0xffffffffu, mv, off));
    if ((tid & 31) == 0) sm[tid >> 5] = mv;
    __syncthreads();
    float M = fmaxf(fmaxf(sm[0], sm[1]), fmaxf(sm[2], sm[3]));
    __syncthreads();

    float sv = 0.f;
    if (tid < NBLK) sv = g_ps[m][row][tid] * expf(pm - M);
    #pragma unroll
    for (int off = 16; off >= 1; off >>= 1)
        sv += __shfl_xor_sync(0xffffffffu, sv, off);
    if ((tid & 31) == 0) sm[tid >> 5] = sv;
    __syncthreads();

    if (tid == 0) {
        const float S = sm[0] + sm[1] + sm[2] + sm[3];
        const float lse = M + logf(S);
        g_tok[m][row] = g_mask[row] ? (g_tgt[m][row] - lse) : 0.f;
    }
}

// -----------------------------------------------------------------------------
// Phase C: per-sequence sums (double, deterministic) + KTO epilogue.
// -----------------------------------------------------------------------------
__global__ void final_kernel(const float* __restrict__ kl,
                             float* __restrict__ out, int out_size)
{
    __shared__ double seq[2][NSEQ];
    const int tid = threadIdx.x;
    const int wid = tid >> 5;
    const int lid = tid & 31;

    if (wid < 8) {
        const int m = wid >> 2;
        const int b = wid & 3;
        double s = 0.0;
        #pragma unroll
        for (int i = 0; i < 16; i++)
            s += (double)g_tok[m][b * TSEQ + i * 32 + lid];
        #pragma unroll
        for (int off = 16; off >= 1; off >>= 1)
            s += __shfl_xor_sync(0xffffffffu, s, off);
        if (lid == 0) seq[m][b] = s;
    }
    __syncthreads();

    if (tid == 0) {
        const double k = (double)kl[0];
        double loss = 0.0, ch = 0.0, rj = 0.0;
        for (int b = 0; b < NSEQ; b++) {
            const double lr   = seq[0][b] - seq[1][b];
            const int    lab  = g_labels[b];
            const double mult = lab ? 1.0 : -1.0;
            const double z    = (double)BETA * (lr - k) * mult;
            const double sg   = 1.0 / (1.0 + exp(-z));
            loss += 1.0 - sg;
            const double rw = (double)BETA * lr;
            if (lab) ch += rw; else rj += rw;
        }
        loss /= (double)R_TOK;
        if (out_size > 0) out[0] = (float)loss;
        if (out_size > 1) out[1] = (float)ch;
        if (out_size > 2) out[2] = (float)rj;
    }
    for (int i = 3 + tid; i < out_size; i += blockDim.x) out[i] = 0.f;
}

// -----------------------------------------------------------------------------
// Launch
// -----------------------------------------------------------------------------
extern "C" void kernel_launch(void* const* d_in, const int* in_sizes, int n_in,
                              void* d_out, int out_size)
{
    int ix = -1, ixr = -1, iw = -1, iwr = -1, ib = -1, ibr = -1;
    int it = -1, il = -1, ikl = -1;
    for (int i = 0; i < n_in; i++) {
        const long long s = in_sizes[i];
        if      (s == (long long)R_TOK * HID) { if (ix < 0) ix = i; else ixr = i; }
        else if (s == (long long)VOC * HID)   { if (iw < 0) iw = i; else iwr = i; }
        else if (s == VOC)                    { if (ib < 0) ib = i; else ibr = i; }
        else if (s == R_TOK)                  { it = i; }
        else if (s == NSEQ)                   { il = i; }
        else if (s == 1)                      { ikl = i; }
    }
    if (ix < 0) ix = 0; if (iw < 0) iw = 1; if (it < 0) it = 2; if (ib < 0) ib = 3;
    if (il < 0) il = 4; if (ixr < 0) ixr = 5; if (iwr < 0) iwr = 6; if (ibr < 0) ibr = 7;
    if (ikl < 0) ikl = 8;

    const float* x      = (const float*)d_in[ix];
    const float* w      = (const float*)d_in[iw];
    const void*  tgt    = d_in[it];
    const float* bias   = (const float*)d_in[ib];
    const void*  labels = d_in[il];
    const float* xr     = (const float*)d_in[ixr];
    const float* wr     = (const float*)d_in[iwr];
    const float* br     = (const float*)d_in[ibr];
    const float* kl     = (const float*)d_in[ikl];

    cudaFuncSetAttribute(gemm_tc_kernel,
                         cudaFuncAttributeMaxDynamicSharedMemorySize, SMEM_TOTAL);

    detect_kernel<<<1, 256>>>(tgt, labels);

    {
        const int totX = 2 * R_TOK * (HID / 4);
        convert_x_kernel<<<(totX + 255) / 256, 256>>>(x, xr);
        const int totW = 2 * VOC * (HID / 4);
        convert_w_kernel<<<(totW + 255) / 256, 256>>>(w, wr);
    }

    gemm_tc_kernel<<<2 * MPAIR * NBLK, 256, SMEM_TOTAL>>>(bias, br);

    dim3 gridB(R_TOK, 2);
    lse_reduce_kernel<<<gridB, 128>>>();

    final_kernel<<<1, 256>>>(kl, (float*)d_out, out_size);
}

// round 16
// speedup vs baseline: 1.1462x; 1.1462x over previous
#include <cuda_runtime.h>
#include <cuda_bf16.h>
#include <cstdint>
#include <math.h>

// Problem constants (B=4, T=512, H=1024, V=32000)
#define R_TOK 2048
#define HID   1024
#define VOC   32000
#define NSEQ  4
#define TSEQ  512

#define KCAT  3072              // [hi | hi | lo] x [hi | lo | hi] concatenated K
#define BM    128
#define BN    256
#define NBLK  (VOC / BN)        // 125
#define MPAIR 8                 // 16 m-blocks in pairs
#define NCHUNK 48               // K chunks (shared by both tiles)
#define NSTAGE 3
#define STAGE_BYTES 65536       // A0 16KB + A1 16KB + B 32KB
#define SMEM_TOTAL (2048 + NSTAGE * STAGE_BYTES)   // 198656

#define BETA 0.1f

// idesc: F32 accum, bf16 A/B, K-major, M=128, N=256
#define MMA_IDESC_N256 0x08400490u

// tcgen05 only exists in arch-specific (sm_103a/f) compilation passes.
#if defined(__CUDA_ARCH_FEAT_SM103_ALL) || defined(__CUDA_ARCH_FEAT_SM100_ALL) || \
    defined(__CUDA_ARCH_FEAT_SM101_ALL) || \
    (defined(__CUDA_ARCH_SPECIFIC__) && (__CUDA_ARCH_SPECIFIC__ >= 1000))
#define HAS_TC 1
#else
#define HAS_TC 0
#endif

// ------------------------------- scratch -----------------------------------
__device__ float g_pm[2][R_TOK][NBLK];
__device__ float g_ps[2][R_TOK][NBLK];
__device__ float g_tgt[2][R_TOK];
__device__ float g_tok[2][R_TOK];
__device__ int   g_target[R_TOK];
__device__ int   g_mask[R_TOK];
__device__ int   g_labels[NSEQ];

__device__ __align__(16) __nv_bfloat16 g_A[2][R_TOK][KCAT];   // 25 MB
__device__ __align__(16) __nv_bfloat16 g_B[2][VOC][KCAT];     // 393 MB

// ------------------------------- PTX helpers -------------------------------
__device__ __forceinline__ uint32_t smem_u32(const void* p) {
    uint32_t a;
    asm("{ .reg .u64 t; cvta.to.shared.u64 t, %1; cvt.u32.u64 %0, t; }"
        : "=r"(a) : "l"(p));
    return a;
}

__device__ __forceinline__ uint32_t sw128(uint32_t o) {
    return o ^ ((o >> 3) & 0x70u);
}

__device__ __forceinline__ void cp16(uint32_t s, const void* g) {
    asm volatile("cp.async.cg.shared.global [%0], [%1], 16;" :: "r"(s), "l"(g));
}

#if HAS_TC
__device__ __forceinline__ uint32_t elect1() {
    uint32_t r;
    asm volatile("{\n\t.reg .pred p;\n\telect.sync _|p, 0xFFFFFFFF;\n\t"
                 "selp.b32 %0, 1, 0, p;\n\t}" : "=r"(r));
    return r;
}

// SW128 K-major descriptor: layout=2, version=1, SBO=64, LBO=1
__device__ __forceinline__ uint64_t mk_desc(uint32_t addr) {
    return ((uint64_t)2 << 61) | ((uint64_t)1 << 46) | ((uint64_t)64 << 32) |
           ((uint64_t)1 << 16) | ((uint64_t)(addr >> 4) & 0x3FFF);
}

__device__ __forceinline__ void mma_f16_ss(uint32_t d, uint64_t a, uint64_t b,
                                           uint32_t en) {
    asm volatile(
        "{\n\t.reg .pred p;\n\tsetp.ne.u32 p, %4, 0;\n\t"
        "tcgen05.mma.cta_group::1.kind::f16 [%0], %1, %2, %3, {%5, %5, %5, %5}, p;\n\t}"
        :: "r"(d), "l"(a), "l"(b), "r"(MMA_IDESC_N256), "r"(en), "r"(0u)
        : "memory");
}

__device__ __forceinline__ void tc_commit(uint32_t m) {
    asm volatile(
        "tcgen05.commit.cta_group::1.mbarrier::arrive::one.shared::cluster.b64 [%0];"
        :: "r"(m) : "memory");
}

__device__ __forceinline__ void cpasync_arrive_noinc(uint32_t m) {
    asm volatile("cp.async.mbarrier.arrive.noinc.shared::cta.b64 [%0];"
                 :: "r"(m) : "memory");
}

#define LDTM_X32(r, addr) \
    asm volatile( \
        "tcgen05.ld.sync.aligned.32x32b.x32.b32 " \
        "{%0, %1, %2, %3, %4, %5, %6, %7, " \
        " %8, %9, %10, %11, %12, %13, %14, %15, " \
        " %16, %17, %18, %19, %20, %21, %22, %23, " \
        " %24, %25, %26, %27, %28, %29, %30, %31}, [%32];" \
        : "=r"((r)[0]),  "=r"((r)[1]),  "=r"((r)[2]),  "=r"((r)[3]), \
          "=r"((r)[4]),  "=r"((r)[5]),  "=r"((r)[6]),  "=r"((r)[7]), \
          "=r"((r)[8]),  "=r"((r)[9]),  "=r"((r)[10]), "=r"((r)[11]), \
          "=r"((r)[12]), "=r"((r)[13]), "=r"((r)[14]), "=r"((r)[15]), \
          "=r"((r)[16]), "=r"((r)[17]), "=r"((r)[18]), "=r"((r)[19]), \
          "=r"((r)[20]), "=r"((r)[21]), "=r"((r)[22]), "=r"((r)[23]), \
          "=r"((r)[24]), "=r"((r)[25]), "=r"((r)[26]), "=r"((r)[27]), \
          "=r"((r)[28]), "=r"((r)[29]), "=r"((r)[30]), "=r"((r)[31]) \
        : "r"(addr))
#endif  // HAS_TC

__device__ __forceinline__ void mbar_init(uint32_t m, uint32_t cnt) {
    asm volatile("mbarrier.init.shared.b64 [%0], %1;" :: "r"(m), "r"(cnt) : "memory");
}

__device__ __forceinline__ void mbar_wait(uint32_t m, uint32_t parity) {
    asm volatile(
        "{\n\t.reg .pred P;\n\t"
        "W_%=:\n\t"
        "mbarrier.try_wait.parity.acquire.cta.shared::cta.b64 P, [%0], %1;\n\t"
        "@!P bra W_%=;\n\t}"
        :: "r"(m), "r"(parity) : "memory");
}

#if !HAS_TC
// mma.sync fallback helpers (baseline sm_80+ instructions)
__device__ __forceinline__ void ldsm4(uint32_t& r0, uint32_t& r1,
                                      uint32_t& r2, uint32_t& r3, uint32_t a) {
    asm volatile("ldmatrix.sync.aligned.m8n8.x4.shared.b16 {%0,%1,%2,%3}, [%4];"
                 : "=r"(r0), "=r"(r1), "=r"(r2), "=r"(r3) : "r"(a));
}

__device__ __forceinline__ void hmma(float* c, uint32_t a0, uint32_t a1,
                                     uint32_t a2, uint32_t a3,
                                     uint32_t b0, uint32_t b1) {
    asm volatile(
        "mma.sync.aligned.m16n8k16.row.col.f32.bf16.bf16.f32 "
        "{%0,%1,%2,%3}, {%4,%5,%6,%7}, {%8,%9}, {%0,%1,%2,%3};"
        : "+f"(c[0]), "+f"(c[1]), "+f"(c[2]), "+f"(c[3])
        : "r"(a0), "r"(a1), "r"(a2), "r"(a3), "r"(b0), "r"(b1));
}
#endif

// -----------------------------------------------------------------------------
// Phase 0: dtype detection + normalization of target / labels (proven in R2)
// -----------------------------------------------------------------------------
__global__ void detect_kernel(const void* __restrict__ tgt_raw,
                              const void* __restrict__ lab_raw)
{
    __shared__ int s_t64;
    const int tid = threadIdx.x;
    const int* t32 = (const int*)tgt_raw;

    if (tid == 0) {
        bool t64 = true;
        for (int k = 0; k < 64; k++)
            if (t32[2 * k + 1] != 0) { t64 = false; break; }
        s_t64 = t64 ? 1 : 0;

        const unsigned int*  li = (const unsigned int*)lab_raw;
        const unsigned char* lb = (const unsigned char*)lab_raw;
        int done = 0;
        {
            bool isf = true;
            for (int b = 0; b < 4; b++) {
                unsigned int u = li[b];
                if (u != 0u && u != 0x3f800000u) { isf = false; break; }
            }
            if (isf) {
                for (int b = 0; b < 4; b++) g_labels[b] = (li[b] != 0u) ? 1 : 0;
                done = 1;
            }
        }
        if (!done && li[0] <= 1u) {
            bool isi = true;
            for (int b = 1; b < 4; b++)
                if (li[b] > 1u) { isi = false; break; }
            if (isi) {
                for (int b = 0; b < 4; b++) g_labels[b] = (int)li[b];
                done = 1;
            }
        }
        if (!done)
            for (int b = 0; b < 4; b++) g_labels[b] = (lb[b] != 0) ? 1 : 0;
    }
    __syncthreads();

    const bool t64 = (s_t64 != 0);
    for (int i = tid; i < R_TOK; i += blockDim.x) {
        int v = t64 ? t32[2 * i] : t32[i];
        const int ign = (v == -100);
        if (v < 0) v = 0;
        if (v > VOC - 1) v = VOC - 1;
        g_target[i] = v;
        g_mask[i]   = ign ? 0 : 1;
    }
}

// -----------------------------------------------------------------------------
// Phase 0b: fp32 -> bf16 hi/lo split into concatenated-K operands.
// A' = [Xhi | Xhi | Xlo], B' = [Whi | Wlo | Whi]
// -----------------------------------------------------------------------------
__device__ __forceinline__ void split4(const float4 v,
                                       __nv_bfloat162& h01, __nv_bfloat162& h23,
                                       __nv_bfloat162& l01, __nv_bfloat162& l23)
{
    __nv_bfloat16 h0 = __float2bfloat16_rn(v.x);
    __nv_bfloat16 h1 = __float2bfloat16_rn(v.y);
    __nv_bfloat16 h2 = __float2bfloat16_rn(v.z);
    __nv_bfloat16 h3 = __float2bfloat16_rn(v.w);
    __nv_bfloat16 l0 = __float2bfloat16_rn(v.x - __bfloat162float(h0));
    __nv_bfloat16 l1 = __float2bfloat16_rn(v.y - __bfloat162float(h1));
    __nv_bfloat16 l2 = __float2bfloat16_rn(v.z - __bfloat162float(h2));
    __nv_bfloat16 l3 = __float2bfloat16_rn(v.w - __bfloat162float(h3));
    h01 = __nv_bfloat162(h0, h1); h23 = __nv_bfloat162(h2, h3);
    l01 = __nv_bfloat162(l0, l1); l23 = __nv_bfloat162(l2, l3);
}

__global__ void convert_w_kernel(const float* __restrict__ w0,
                                 const float* __restrict__ w1)
{
    const int QPR = HID / 4;                     // 256 quads/row
    const int per_model = VOC * QPR;
    int id = blockIdx.x * blockDim.x + threadIdx.x;
    if (id >= 2 * per_model) return;
    const int m = id / per_model;
    const int r = (id % per_model) / QPR;
    const int q = id % QPR;
    const float* W = m ? w1 : w0;
    const float4 v = *(const float4*)(W + (size_t)r * HID + q * 4);
    __nv_bfloat162 h01, h23, l01, l23;
    split4(v, h01, h23, l01, l23);
    __nv_bfloat16* row = &g_B[m][r][0];
    *(__nv_bfloat162*)(row + q * 4 + 0)        = h01;   // seg0: hi
    *(__nv_bfloat162*)(row + q * 4 + 2)        = h23;
    *(__nv_bfloat162*)(row + HID + q * 4 + 0)  = l01;   // seg1: lo
    *(__nv_bfloat162*)(row + HID + q * 4 + 2)  = l23;
    *(__nv_bfloat162*)(row + 2*HID + q * 4 + 0) = h01;  // seg2: hi
    *(__nv_bfloat162*)(row + 2*HID + q * 4 + 2) = h23;
}

__global__ void convert_x_kernel(const float* __restrict__ x0,
                                 const float* __restrict__ x1)
{
    const int QPR = HID / 4;
    const int per_model = R_TOK * QPR;
    int id = blockIdx.x * blockDim.x + threadIdx.x;
    if (id >= 2 * per_model) return;
    const int m = id / per_model;
    const int r = (id % per_model) / QPR;
    const int q = id % QPR;
    const float* X = m ? x1 : x0;
    const float4 v = *(const float4*)(X + (size_t)r * HID + q * 4);
    __nv_bfloat162 h01, h23, l01, l23;
    split4(v, h01, h23, l01, l23);
    __nv_bfloat16* row = &g_A[m][r][0];
    *(__nv_bfloat162*)(row + q * 4 + 0)        = h01;   // seg0: hi
    *(__nv_bfloat162*)(row + q * 4 + 2)        = h23;
    *(__nv_bfloat162*)(row + HID + q * 4 + 0)  = h01;   // seg1: hi
    *(__nv_bfloat162*)(row + HID + q * 4 + 2)  = h23;
    *(__nv_bfloat162*)(row + 2*HID + q * 4 + 0) = l01;  // seg2: lo
    *(__nv_bfloat162*)(row + 2*HID + q * 4 + 2) = l23;
}

// -----------------------------------------------------------------------------
// Phase A: bf16 GEMM. Each CTA: TWO 128-row M-tiles x one 256-col N-block,
// INTERLEAVED over 48 shared-B chunks. N=256 MMA dispatches (floor 128 cyc),
// D0/D1 in TMEM cols 0-255 / 256-511. Warps 1-4 load (A0+A1+B = 64KB/chunk),
// warp 0 issues; 3-stage pipeline; both epilogues in parallel on 8 warps.
// grid.x = 2*MPAIR*NBLK = 2000; block = 256.
// -----------------------------------------------------------------------------
extern __shared__ char dsmem[];

__global__ void __launch_bounds__(256, 1)
gemm_tc_kernel(const float* __restrict__ b_pol, const float* __restrict__ b_ref)
{
    const int bx    = blockIdx.x;
    const int mpair = bx & (MPAIR - 1);
    const int t     = bx >> 3;
    const int nblk  = t % NBLK;
    const int model = t / NBLK;
    const int rb0   = mpair * 256;
    const int rb1   = rb0 + 128;
    const int cb    = nblk * BN;
    const float* __restrict__ Bv = model ? b_ref : b_pol;

    const int tid = threadIdx.x;
    const int wid = tid >> 5;
    const int lid = tid & 31;

    const uint32_t smem_base = smem_u32(dsmem);
    float* bias_s = (float*)(dsmem + 1024);

    const char* Agm0 = (const char*)&g_A[model][rb0][0];
    const char* Agm1 = (const char*)&g_A[model][rb1][0];
    const char* Bgm  = (const char*)&g_B[model][cb][0];
    const size_t rowbytes = (size_t)KCAT * 2;

#if HAS_TC
    // ======================= tcgen05 path (sm_103a) ==========================
    // mbarriers: mma[s] at +s*8 (cnt 1, s<3); tile_done at +48;
    // full[s] at +64+s*8 (cnt 128). tmem ptr at +32. bias at +1024.
    // Stages at +2048: A0 16KB | A1 16KB | B 32KB.
    if (tid == 0) {
        #pragma unroll
        for (int s = 0; s < NSTAGE; s++) {
            mbar_init(smem_base + s * 8, 1);
            mbar_init(smem_base + 64 + s * 8, 128);
        }
        mbar_init(smem_base + 48, 1);
    }
    if (wid == 0) {
        asm volatile(
            "tcgen05.alloc.cta_group::1.sync.aligned.shared::cta.b32 [%0], %1;"
            :: "r"(smem_base + 32), "r"(512) : "memory");
    }
    if (tid < BN) bias_s[tid] = Bv[cb + tid];
    __syncthreads();
    uint32_t tmem;
    asm volatile("ld.shared.b32 %0, [%1];" : "=r"(tmem) : "r"(smem_base + 32));

    if (wid >= 1 && wid <= 4) {
        // ------------- loader warps (4): 32 cp16/thread/chunk --------------
        const int ltid = tid - 32;                  // 0..127
        const int xq   = ltid & 7;                  // 16B column
        const int r0   = ltid >> 3;                 // base row 0..15
        const uint32_t sw_x  = (uint32_t)(xq * 16) ^ (uint32_t)((r0 & 7) * 16);
        const uint32_t off0  = (uint32_t)r0 * 128 + sw_x;   // + i*2048 per step
        const size_t   tbase = (size_t)r0 * rowbytes + xq * 16;
        const char*    a0g0  = Agm0 + tbase;
        const char*    a1g0  = Agm1 + tbase;
        const char*    bg0   = Bgm + tbase;
        const size_t   gstep = 16 * rowbytes;

        for (int c = 0; c < NCHUNK; c++) {
            const int s = c - (c / 3) * 3;          // c % 3
            if (c >= NSTAGE)
                mbar_wait(smem_base + s * 8, (uint32_t)((c / 3 - 1) & 1));
            const uint32_t sb = smem_base + 2048 + s * STAGE_BYTES;
            const uint32_t a0s = sb + off0;
            const uint32_t a1s = a0s + 16384;
            const uint32_t bs  = a0s + 32768;
            const char* a0g = a0g0 + (size_t)c * 128;
            const char* a1g = a1g0 + (size_t)c * 128;
            const char* bg  = bg0  + (size_t)c * 128;
            #pragma unroll
            for (int i = 0; i < 8; i++)             // A0 rows r0+16i
                cp16(a0s + i * 2048, a0g + i * gstep);
            #pragma unroll
            for (int i = 0; i < 8; i++)             // A1 rows r0+16i
                cp16(a1s + i * 2048, a1g + i * gstep);
            #pragma unroll
            for (int i = 0; i < 16; i++)            // B rows r0+16i (256)
                cp16(bs + i * 2048, bg + i * gstep);
            cpasync_arrive_noinc(smem_base + 64 + s * 8);
        }
    } else if (wid == 0) {
        // ---------------- issuer warp ----------------
        const uint32_t is_issuer = elect1();
        for (int c = 0; c < NCHUNK; c++) {
            const int s = c - (c / 3) * 3;
            mbar_wait(smem_base + 64 + s * 8, (uint32_t)((c / 3) & 1));
            if (is_issuer) {
                asm volatile("fence.proxy.async.shared::cta;" ::: "memory");
                const uint32_t base = smem_base + 2048 + s * STAGE_BYTES;
                const uint64_t a0d = mk_desc(base);
                const uint64_t a1d = mk_desc(base + 16384);
                const uint64_t bd  = mk_desc(base + 32768);
                #pragma unroll
                for (int ks = 0; ks < 4; ks++) {
                    const uint32_t en = (c > 0 || ks > 0) ? 1u : 0u;
                    mma_f16_ss(tmem,       a0d + ks * 2, bd + ks * 2, en);
                    mma_f16_ss(tmem + 256, a1d + ks * 2, bd + ks * 2, en);
                }
                tc_commit(smem_base + s * 8);
                if (c == NCHUNK - 1) tc_commit(smem_base + 48);
            }
        }
    }

    // wait for all MMAs, then both tiles' epilogues in parallel (8 warps)
    mbar_wait(smem_base + 48, 0u);
    asm volatile("tcgen05.fence::after_thread_sync;" ::: "memory");
    {
        const int  tile = wid >> 2;                  // 0: warps 0-3, 1: warps 4-7
        const int  row  = (tile ? rb1 : rb0) + (wid & 3) * 32 + lid;
        const uint32_t dtm = tmem + (tile ? 256u : 0u);
        const int tg  = g_target[row];
        const int loc = tg - cb;
        float rmax = -INFINITY, rsum = 0.f, tl = 0.f;
        uint32_t r[32];
        #pragma unroll
        for (int b = 0; b < 8; b++) {
            LDTM_X32(r, dtm + b * 32);
            asm volatile("tcgen05.wait::ld.sync.aligned;" ::: "memory");
            float v[32];
            float bmax = -INFINITY;
            #pragma unroll
            for (int j = 0; j < 32; j++) {
                v[j] = __uint_as_float(r[j]) + bias_s[b * 32 + j];
                bmax = fmaxf(bmax, v[j]);
            }
            const float nm = fmaxf(rmax, bmax);
            rsum *= __expf(rmax - nm);
            float s = 0.f;
            #pragma unroll
            for (int j = 0; j < 32; j++) s += __expf(v[j] - nm);
            rsum += s;
            rmax = nm;
            if ((loc >> 5) == b) {
                #pragma unroll
                for (int j = 0; j < 32; j++)
                    if ((loc & 31) == j) tl = v[j];
            }
        }
        g_pm[model][row][nblk] = rmax;
        g_ps[model][row][nblk] = rsum;
        if (loc >= 0 && loc < BN) g_tgt[model][row] = tl;
    }

    __syncthreads();
    if (wid == 0) {
        asm volatile("tcgen05.dealloc.cta_group::1.sync.aligned.b32 %0, %1;"
                     :: "r"(tmem), "r"(512));
    }
#else
    // ================== mma.sync fallback (baseline sm_103) ==================
    // sequential two tiles, 3-stage pipeline on the new layout (A at +0, B at
    // +32768 within each 64KB stage).
    auto load_chunk = [&](const char* Ag, int c, int s) {
        const uint32_t abase = smem_base + 2048 + s * STAGE_BYTES;
        const uint32_t bbase = abase + 32768;
        const char* ag = Ag + (size_t)c * 128;
        const char* bg = Bgm + (size_t)c * 128;
        #pragma unroll
        for (int i = 0; i < 4; i++) {               // A: 1024 x 16B
            const int q = tid + 256 * i;
            const int row = q >> 3, x = q & 7;
            cp16(abase + sw128(row * 128 + x * 16), ag + (size_t)row * rowbytes + x * 16);
        }
        #pragma unroll
        for (int i = 0; i < 8; i++) {               // B: 2048 x 16B
            const int q = tid + 256 * i;
            const int row = q >> 3, x = q & 7;
            cp16(bbase + sw128(row * 128 + x * 16), bg + (size_t)row * rowbytes + x * 16);
        }
        asm volatile("cp.async.commit_group;" ::: "memory");
    };

    const int wr = wid & 3;
    const int wc = wid >> 2;
    const int koffA = (lid >> 4) * 16;
    const int xA    = (lid & 7) << 4;
    const int rA0   = wr * 32 + (lid & 15);
    const int rbB   = (lid >> 4) * 8 + (lid & 7);
    const int koffB = ((lid >> 3) & 1) * 16;
    const int xB    = (rbB & 7) << 4;
    const int brow  = wc * 128 + rbB;

    for (int tile = 0; tile < 2; tile++) {
        const int rb = rb0 + tile * 128;
        const char* Ag = tile ? Agm1 : Agm0;

        load_chunk(Ag, 0, 0);
        load_chunk(Ag, 1, 1);

        float acc[2][16][4];
        #pragma unroll
        for (int a = 0; a < 2; a++)
            #pragma unroll
            for (int b = 0; b < 16; b++)
                #pragma unroll
                for (int d = 0; d < 4; d++) acc[a][b][d] = 0.f;

        for (int c = 0; c < NCHUNK; c++) {
            asm volatile("cp.async.wait_group 1;" ::: "memory");
            __syncthreads();
            const int s = c - (c / 3) * 3;
            const uint32_t sb  = smem_base + 2048 + s * STAGE_BYTES;
            const uint32_t aA0 = sb + rA0 * 128;
            const uint32_t aA1 = sb + (rA0 + 16) * 128;
            const uint32_t bB  = sb + 32768 + brow * 128;
            #pragma unroll
            for (int ks = 0; ks < 4; ks++) {
                const int kb = ks * 32;
                uint32_t a0[4], a1[4];
                ldsm4(a0[0], a0[1], a0[2], a0[3], aA0 + ((kb + koffA) ^ xA));
                ldsm4(a1[0], a1[1], a1[2], a1[3], aA1 + ((kb + koffA) ^ xA));
                #pragma unroll
                for (int p = 0; p < 8; p++) {
                    uint32_t b0, b1, b2, b3;
                    ldsm4(b0, b1, b2, b3, bB + p * 2048 + ((kb + koffB) ^ xB));
                    hmma(acc[0][2*p],     a0[0], a0[1], a0[2], a0[3], b0, b1);
                    hmma(acc[1][2*p],     a1[0], a1[1], a1[2], a1[3], b0, b1);
                    hmma(acc[0][2*p + 1], a0[0], a0[1], a0[2], a0[3], b2, b3);
                    hmma(acc[1][2*p + 1], a1[0], a1[1], a1[2], a1[3], b2, b3);
                }
            }
            __syncthreads();
            const int n = c + 2;
            if (n < NCHUNK) load_chunk(Ag, n, n - (n / 3) * 3);
            else asm volatile("cp.async.commit_group;" ::: "memory");
        }
        asm volatile("cp.async.wait_group 0;" ::: "memory");
        __syncthreads();

        float* bias_f = (float*)(dsmem + 1024);
        if (tid < BN) bias_f[tid] = Bv[cb + tid];
        float* rmx = (float*)(dsmem + 2048);
        float* rsm = rmx + 256;
        float* rtl = rsm + 256;
        __syncthreads();

        #pragma unroll
        for (int mi = 0; mi < 2; mi++) {
            #pragma unroll
            for (int half = 0; half < 2; half++) {
                const int rloc = wr * 32 + mi * 16 + (lid >> 2) + half * 8;
                const int loc  = g_target[rb + rloc] - cb;
                float m = -INFINITY;
                #pragma unroll
                for (int nt = 0; nt < 16; nt++) {
                    #pragma unroll
                    for (int j = 0; j < 2; j++) {
                        const int gcol = wc * 128 + nt * 8 + (lid & 3) * 2 + j;
                        m = fmaxf(m, acc[mi][nt][half * 2 + j] + bias_f[gcol]);
                    }
                }
                float s = 0.f, tl = 0.f;
                #pragma unroll
                for (int nt = 0; nt < 16; nt++) {
                    #pragma unroll
                    for (int j = 0; j < 2; j++) {
                        const int gcol = wc * 128 + nt * 8 + (lid & 3) * 2 + j;
                        const float v = acc[mi][nt][half * 2 + j] + bias_f[gcol];
                        s += __expf(v - m);
                        if (gcol == loc) tl = v;
                    }
                }
                #pragma unroll
                for (int off = 1; off <= 2; off <<= 1) {
                    const float mo = __shfl_xor_sync(0xffffffffu, m, off);
                    const float so = __shfl_xor_sync(0xffffffffu, s, off);
                    const float nm = fmaxf(m, mo);
                    s = s * __expf(m - nm) + so * __expf(mo - nm);
                    m = nm;
                    tl += __shfl_xor_sync(0xffffffffu, tl, off);
                }
                if ((lid & 3) == 0) {
                    rmx[rloc * 2 + wc] = m;
                    rsm[rloc * 2 + wc] = s;
                    rtl[rloc * 2 + wc] = tl;
                }
            }
        }
        __syncthreads();

        if (tid < 128) {
            const int row = rb + tid;
            const float m0 = rmx[tid * 2], m1 = rmx[tid * 2 + 1];
            const float M  = fmaxf(m0, m1);
            const float S  = rsm[tid * 2] * __expf(m0 - M) +
                             rsm[tid * 2 + 1] * __expf(m1 - M);
            g_pm[model][row][nblk] = M;
            g_ps[model][row][nblk] = S;
            const int loc = g_target[row] - cb;
            if (loc >= 0 && loc < BN)
                g_tgt[model][row] = rtl[tid * 2] + rtl[tid * 2 + 1];
        }
        __syncthreads();
    }
#endif
}

// -----------------------------------------------------------------------------
// Phase B: merge the 125 per-nblock partials -> full LSE -> per-token logprob.
// -----------------------------------------------------------------------------
__global__ void lse_reduce_kernel()
{
    const int row = blockIdx.x;
    const int m   = blockIdx.y;
    const int tid = threadIdx.x;

    __shared__ float sm[4];

    float pm = -INFINITY;
    if (tid < NBLK) pm = g_pm[m][row][tid];

    float mv = pm;
    #pragma unroll
    for (int off = 16; off >= 1; off >>= 1)
        mv = fmaxf(mv, __shfl_xor_sync(0xffffffffu, mv, off));
    if ((tid & 31) == 0) sm[tid >> 5] = mv;
    __syncthreads();
    float M = fmaxf(fmaxf(sm[0], sm[1]), fmaxf(sm[2], sm[3]));
    __syncthreads();

    float sv = 0.f;
    if (tid < NBLK) sv = g_ps[m][row][tid] * expf(pm - M);
    #pragma unroll
    for (int off = 16; off >= 1; off >>= 1)
        sv += __shfl_xor_sync(0xffffffffu, sv, off);
    if ((tid & 31) == 0) sm[tid >> 5] = sv;
    __syncthreads();

    if (tid == 0) {
        const float S = sm[0] + sm[1] + sm[2] + sm[3];
        const float lse = M + logf(S);
        g_tok[m][row] = g_mask[row] ? (g_tgt[m][row] - lse) : 0.f;
    }
}

// -----------------------------------------------------------------------------
// Phase C: per-sequence sums (double, deterministic) + KTO epilogue.
// -----------------------------------------------------------------------------
__global__ void final_kernel(const float* __restrict__ kl,
                             float* __restrict__ out, int out_size)
{
    __shared__ double seq[2][NSEQ];
    const int tid = threadIdx.x;
    const int wid = tid >> 5;
    const int lid = tid & 31;

    if (wid < 8) {
        const int m = wid >> 2;
        const int b = wid & 3;
        double s = 0.0;
        #pragma unroll
        for (int i = 0; i < 16; i++)
            s += (double)g_tok[m][b * TSEQ + i * 32 + lid];
        #pragma unroll
        for (int off = 16; off >= 1; off >>= 1)
            s += __shfl_xor_sync(0xffffffffu, s, off);
        if (lid == 0) seq[m][b] = s;
    }
    __syncthreads();

    if (tid == 0) {
        const double k = (double)kl[0];
        double loss = 0.0, ch = 0.0, rj = 0.0;
        for (int b = 0; b < NSEQ; b++) {
            const double lr   = seq[0][b] - seq[1][b];
            const int    lab  = g_labels[b];
            const double mult = lab ? 1.0 : -1.0;
            const double z    = (double)BETA * (lr - k) * mult;
            const double sg   = 1.0 / (1.0 + exp(-z));
            loss += 1.0 - sg;
            const double rw = (double)BETA * lr;
            if (lab) ch += rw; else rj += rw;
        }
        loss /= (double)R_TOK;
        if (out_size > 0) out[0] = (float)loss;
        if (out_size > 1) out[1] = (float)ch;
        if (out_size > 2) out[2] = (float)rj;
    }
    for (int i = 3 + tid; i < out_size; i += blockDim.x) out[i] = 0.f;
}

// -----------------------------------------------------------------------------
// Launch
// -----------------------------------------------------------------------------
extern "C" void kernel_launch(void* const* d_in, const int* in_sizes, int n_in,
                              void* d_out, int out_size)
{
    int ix = -1, ixr = -1, iw = -1, iwr = -1, ib = -1, ibr = -1;
    int it = -1, il = -1, ikl = -1;
    for (int i = 0; i < n_in; i++) {
        const long long s = in_sizes[i];
        if      (s == (long long)R_TOK * HID) { if (ix < 0) ix = i; else ixr = i; }
        else if (s == (long long)VOC * HID)   { if (iw < 0) iw = i; else iwr = i; }
        else if (s == VOC)                    { if (ib < 0) ib = i; else ibr = i; }
        else if (s == R_TOK)                  { it = i; }
        else if (s == NSEQ)                   { il = i; }
        else if (s == 1)                      { ikl = i; }
    }
    if (ix < 0) ix = 0; if (iw < 0) iw = 1; if (it < 0) it = 2; if (ib < 0) ib = 3;
    if (il < 0) il = 4; if (ixr < 0) ixr = 5; if (iwr < 0) iwr = 6; if (ibr < 0) ibr = 7;
    if (ikl < 0) ikl = 8;

    const float* x      = (const float*)d_in[ix];
    const float* w      = (const float*)d_in[iw];
    const void*  tgt    = d_in[it];
    const float* bias   = (const float*)d_in[ib];
    const void*  labels = d_in[il];
    const float* xr     = (const float*)d_in[ixr];
    const float* wr     = (const float*)d_in[iwr];
    const float* br     = (const float*)d_in[ibr];
    const float* kl     = (const float*)d_in[ikl];

    cudaFuncSetAttribute(gemm_tc_kernel,
                         cudaFuncAttributeMaxDynamicSharedMemorySize, SMEM_TOTAL);

    detect_kernel<<<1, 256>>>(tgt, labels);

    {
        const int totX = 2 * R_TOK * (HID / 4);
        convert_x_kernel<<<(totX + 255) / 256, 256>>>(x, xr);
        const int totW = 2 * VOC * (HID / 4);
        convert_w_kernel<<<(totW + 255) / 256, 256>>>(w, wr);
    }

    gemm_tc_kernel<<<2 * MPAIR * NBLK, 256, SMEM_TOTAL>>>(bias, br);

    dim3 gridB(R_TOK, 2);
    lse_reduce_kernel<<<gridB, 128>>>();

    final_kernel<<<1, 256>>>(kl, (float*)d_out, out_size);
}